// round 16
// baseline (speedup 1.0000x reference)
#include <cuda_runtime.h>
#include <cstdint>

#define T_LEN   1024
#define B_TOT   512
#define CL      4          // cluster size (gate-row split)
#define BPC     16         // batch per cluster
#define MSL     32         // m-slice per CTA (128 / CL)
#define HPITCH  132        // h row pitch (floats): batch stride = 4 banks
#define WPITCH  516        // weight row pitch: [m][4 gates x 128 k] + 4 pad
#define NTHREADS 512       // tid = m_l*16 + ks*4 + bb : 32 m x 4 k-quarters x 4 bb
                           // each thread: 4 batches {bb,bb+4,bb+8,bb+12}, quarter of k

#define W_FLOATS   (32 * WPITCH)
#define H_FLOATS   (2 * BPC * HPITCH)
#define SMEM_FLOATS (3 * W_FLOATS + 2 * H_FLOATS + 2 * BPC)
#define SMEM_BYTES (SMEM_FLOATS * 4)   // 232,064 B <= 232,448 cap

// ---------- f32x2 packed FMA (FFMA2) ----------
__device__ __forceinline__ unsigned long long ffma2(unsigned long long a,
                                                    unsigned long long b,
                                                    unsigned long long c) {
    unsigned long long d;
    asm("fma.rn.f32x2 %0, %1, %2, %3;" : "=l"(d) : "l"(a), "l"(b), "l"(c));
    return d;
}
__device__ __forceinline__ float2 unpk(unsigned long long v) {
    float2 r;
    asm("mov.b64 {%0, %1}, %2;" : "=f"(r.x), "=f"(r.y) : "l"(v));
    return r;
}

// ---------- activations: ex2.approx + Newton-refined reciprocal ----------
__device__ __forceinline__ float rcp_nr(float x) {
    float r; asm("rcp.approx.f32 %0, %1;" : "=f"(r) : "f"(x));
    r = r * fmaf(-x, r, 2.0f);
    return r;
}
__device__ __forceinline__ float ex2f(float x) {
    float r; asm("ex2.approx.f32 %0, %1;" : "=f"(r) : "f"(x)); return r;
}
__device__ __forceinline__ float sigf(float x) {
    return rcp_nr(1.0f + ex2f(-1.4426950408889634f * x));
}
__device__ __forceinline__ float tanh_(float x) {
    return fmaf(-2.0f, rcp_nr(1.0f + ex2f(2.8853900817779268f * x)), 1.0f);
}

// ---------- cluster helpers ----------
__device__ __forceinline__ uint32_t mapa_sh(uint32_t addr, uint32_t rank) {
    uint32_t r;
    asm("mapa.shared::cluster.u32 %0, %1, %2;" : "=r"(r) : "r"(addr), "r"(rank));
    return r;
}
__device__ __forceinline__ void st_cluster_f32(uint32_t addr, float v) {
    asm volatile("st.shared::cluster.f32 [%0], %1;" :: "r"(addr), "f"(v) : "memory");
}
__device__ __forceinline__ void cluster_arrive_() {
    asm volatile("barrier.cluster.arrive.aligned;" ::: "memory");
}
__device__ __forceinline__ void cluster_wait_() {
    asm volatile("barrier.cluster.wait.aligned;" ::: "memory");
}

// 4 gates x 4 batches over this thread's 8 k-chunks (ks folded into hb/wb).
// a[g*4+b] accumulates f32x2 partial sums.
__device__ __forceinline__ void dot4x4(const float* __restrict__ hb,
                                       const float* __restrict__ wb,
                                       unsigned long long* __restrict__ a) {
#pragma unroll
    for (int q = 0; q < 4; ++q) {
#pragma unroll
        for (int j = 0; j < 2; ++j) {
            const int o = q * 32 + j * 4;
            ulonglong2 w0 = *reinterpret_cast<const ulonglong2*>(wb + o);
            ulonglong2 w1 = *reinterpret_cast<const ulonglong2*>(wb + 128 + o);
            ulonglong2 w2 = *reinterpret_cast<const ulonglong2*>(wb + 256 + o);
            ulonglong2 w3 = *reinterpret_cast<const ulonglong2*>(wb + 384 + o);
            ulonglong2 h0 = *reinterpret_cast<const ulonglong2*>(hb + o);
            ulonglong2 h1 = *reinterpret_cast<const ulonglong2*>(hb + 4 * HPITCH + o);
            ulonglong2 h2 = *reinterpret_cast<const ulonglong2*>(hb + 8 * HPITCH + o);
            ulonglong2 h3 = *reinterpret_cast<const ulonglong2*>(hb + 12 * HPITCH + o);
            a[0]  = ffma2(w0.x, h0.x, a[0]);  a[0]  = ffma2(w0.y, h0.y, a[0]);
            a[1]  = ffma2(w0.x, h1.x, a[1]);  a[1]  = ffma2(w0.y, h1.y, a[1]);
            a[2]  = ffma2(w0.x, h2.x, a[2]);  a[2]  = ffma2(w0.y, h2.y, a[2]);
            a[3]  = ffma2(w0.x, h3.x, a[3]);  a[3]  = ffma2(w0.y, h3.y, a[3]);
            a[4]  = ffma2(w1.x, h0.x, a[4]);  a[4]  = ffma2(w1.y, h0.y, a[4]);
            a[5]  = ffma2(w1.x, h1.x, a[5]);  a[5]  = ffma2(w1.y, h1.y, a[5]);
            a[6]  = ffma2(w1.x, h2.x, a[6]);  a[6]  = ffma2(w1.y, h2.y, a[6]);
            a[7]  = ffma2(w1.x, h3.x, a[7]);  a[7]  = ffma2(w1.y, h3.y, a[7]);
            a[8]  = ffma2(w2.x, h0.x, a[8]);  a[8]  = ffma2(w2.y, h0.y, a[8]);
            a[9]  = ffma2(w2.x, h1.x, a[9]);  a[9]  = ffma2(w2.y, h1.y, a[9]);
            a[10] = ffma2(w2.x, h2.x, a[10]); a[10] = ffma2(w2.y, h2.y, a[10]);
            a[11] = ffma2(w2.x, h3.x, a[11]); a[11] = ffma2(w2.y, h3.y, a[11]);
            a[12] = ffma2(w3.x, h0.x, a[12]); a[12] = ffma2(w3.y, h0.y, a[12]);
            a[13] = ffma2(w3.x, h1.x, a[13]); a[13] = ffma2(w3.y, h1.y, a[13]);
            a[14] = ffma2(w3.x, h2.x, a[14]); a[14] = ffma2(w3.y, h2.y, a[14]);
            a[15] = ffma2(w3.x, h3.x, a[15]); a[15] = ffma2(w3.y, h3.y, a[15]);
        }
    }
}

// collapse f32x2 + combine 4 k-quarters (ks = lane bits 2-3)
__device__ __forceinline__ float ksum(unsigned long long acc) {
    float2 s = unpk(acc);
    float v = s.x + s.y;
    v += __shfl_xor_sync(0xffffffffu, v, 4);
    v += __shfl_xor_sync(0xffffffffu, v, 8);
    return v;
}

extern "C" __global__ void __launch_bounds__(NTHREADS, 1) __cluster_dims__(CL, 1, 1)
lstm_persistent_kernel(const float* __restrict__ x,
                       const float* __restrict__ wih1, const float* __restrict__ whh1,
                       const float* __restrict__ bih1, const float* __restrict__ bhh1,
                       const float* __restrict__ wih2, const float* __restrict__ whh2,
                       const float* __restrict__ bih2, const float* __restrict__ bhh2,
                       const float* __restrict__ wout, const float* __restrict__ bout,
                       float* __restrict__ out) {
    extern __shared__ float sm[];
    float* W1  = sm;
    float* W2  = W1 + W_FLOATS;
    float* W3  = W2 + W_FLOATS;
    float* h1d = W3 + W_FLOATS;        // [2][16][HPITCH]
    float* h2d = h1d + H_FLOATS;
    float* xs  = h2d + H_FLOATS;       // [2][16]

    const int tid = threadIdx.x;
    uint32_t rank;
    asm("mov.u32 %0, %%cluster_ctarank;" : "=r"(rank));
    const int cid = blockIdx.x / CL;
    const int m_l = tid >> 4;          // 0..31
    const int ks  = (tid >> 2) & 3;    // k-quarter (32B-group interleave)
    const int bb  = tid & 3;           // batches bb, bb+4, bb+8, bb+12
    const int m_g = (int)rank * MSL + m_l;

    // ---- load gate-row slices, gate-interleaved: W[m][g*128 + k] ----
    for (int i = tid; i < 4096; i += NTHREADS) {
        int k4 = i & 31, g = (i >> 5) & 3, mi = i >> 7;
        int j = g * 128 + (int)rank * MSL + mi;
        int dst = mi * WPITCH + g * 128;
        reinterpret_cast<float4*>(W1 + dst)[k4] =
            reinterpret_cast<const float4*>(whh1 + (size_t)j * 128)[k4];
        reinterpret_cast<float4*>(W2 + dst)[k4] =
            reinterpret_cast<const float4*>(wih2 + (size_t)j * 128)[k4];
        reinterpret_cast<float4*>(W3 + dst)[k4] =
            reinterpret_cast<const float4*>(whh2 + (size_t)j * 128)[k4];
    }
    for (int i = tid; i < 2 * H_FLOATS; i += NTHREADS) h1d[i] = 0.0f;
    if (tid < BPC) xs[tid] = x[(size_t)(cid * BPC + tid) * T_LEN + 0];
    __syncthreads();
    cluster_arrive_(); cluster_wait_();

    // gate constants (order i, f, g, o), shared by the 4 batches
    const int ji = m_g, jf = 128 + m_g, jg = 256 + m_g, jo = 384 + m_g;
    const float b1c[4] = { bih1[ji] + bhh1[ji], bih1[jf] + bhh1[jf],
                           bih1[jg] + bhh1[jg], bih1[jo] + bhh1[jo] };
    const float wic[4] = { wih1[ji], wih1[jf], wih1[jg], wih1[jo] };
    const float b2c[4] = { bih2[ji] + bhh2[ji], bih2[jf] + bhh2[jf],
                           bih2[jg] + bhh2[jg], bih2[jo] + bhh2[jo] };
    const float boutv = bout[0];

    // per-thread weight bases with ks fold (ks*8 floats = 32B group)
    const float* w1r = W1 + m_l * WPITCH + ks * 8;
    const float* w2r = W2 + m_l * WPITCH + ks * 8;
    const float* w3r = W3 + m_l * WPITCH + ks * 8;

    // store targets: thread ks stores to CTA ks (covers all 4 CTAs incl. self)
    uint32_t h1_sa = (uint32_t)__cvta_generic_to_shared(h1d);
    uint32_t h2_sa = (uint32_t)__cvta_generic_to_shared(h2d);
    const uint32_t t1 = mapa_sh(h1_sa, (uint32_t)ks);
    const uint32_t t2 = mapa_sh(h2_sa, (uint32_t)ks);

    // output phase: warp wb (0..15) handles batch wb; lane covers 4 dims
    const int wb = tid >> 5, lane = tid & 31;
    const float4 wo4 = reinterpret_cast<const float4*>(wout)[lane];
    float* const out_b = out + (size_t)(cid * BPC + wb) * T_LEN;

    float c1[4] = {0, 0, 0, 0}, c2[4] = {0, 0, 0, 0};

    for (int t = 0; t < T_LEN; ++t) {
        const int rp = t & 1, wp = rp ^ 1;
        float xnext = 0.0f;
        if (tid < BPC && t + 1 < T_LEN)
            xnext = x[(size_t)(cid * BPC + tid) * T_LEN + t + 1];
        float xc[4];
#pragma unroll
        for (int jb = 0; jb < 4; ++jb) xc[jb] = xs[rp * BPC + bb + 4 * jb];

        // -------- layer 1: W_hh1 h1[rp] + W_ih1 x + b --------
        unsigned long long a[16];
#pragma unroll
        for (int i = 0; i < 16; ++i) a[i] = 0;
        dot4x4(h1d + (rp * BPC + bb) * HPITCH + ks * 8, w1r, a);

        float h1v[4];
#pragma unroll
        for (int jb = 0; jb < 4; ++jb) {
            float pi = ksum(a[jb])      + fmaf(wic[0], xc[jb], b1c[0]);
            float pf = ksum(a[4 + jb])  + fmaf(wic[1], xc[jb], b1c[1]);
            float pg = ksum(a[8 + jb])  + fmaf(wic[2], xc[jb], b1c[2]);
            float po = ksum(a[12 + jb]) + fmaf(wic[3], xc[jb], b1c[3]);
            c1[jb] = fmaf(sigf(pf), c1[jb], sigf(pi) * tanh_(pg));
            h1v[jb] = sigf(po) * tanh_(c1[jb]);
        }
        {
            const uint32_t off0 = (uint32_t)(((wp * BPC + bb) * HPITCH + m_g) * 4);
#pragma unroll
            for (int jb = 0; jb < 4; ++jb)
                st_cluster_f32(t1 + off0 + (uint32_t)(jb * 4 * HPITCH * 4), h1v[jb]);
        }
        if (tid < BPC) xs[wp * BPC + tid] = xnext;
        cluster_arrive_();

        // -------- layer 2 part A (legal pre-wait): W_hh2 h2[rp] --------
#pragma unroll
        for (int i = 0; i < 16; ++i) a[i] = 0;
        dot4x4(h2d + (rp * BPC + bb) * HPITCH + ks * 8, w3r, a);

        cluster_wait_();   // h1[wp] from all CTAs now visible

        // -------- layer 2 part B: += W_ih2 h1[wp] --------
        dot4x4(h1d + (wp * BPC + bb) * HPITCH + ks * 8, w2r, a);

        float h2v[4];
#pragma unroll
        for (int jb = 0; jb < 4; ++jb) {
            float pi = ksum(a[jb])      + b2c[0];
            float pf = ksum(a[4 + jb])  + b2c[1];
            float pg = ksum(a[8 + jb])  + b2c[2];
            float po = ksum(a[12 + jb]) + b2c[3];
            c2[jb] = fmaf(sigf(pf), c2[jb], sigf(pi) * tanh_(pg));
            h2v[jb] = sigf(po) * tanh_(c2[jb]);
        }
        {
            const uint32_t off0 = (uint32_t)(((wp * BPC + bb) * HPITCH + m_g) * 4);
#pragma unroll
            for (int jb = 0; jb < 4; ++jb)
                st_cluster_f32(t2 + off0 + (uint32_t)(jb * 4 * HPITCH * 4), h2v[jb]);
        }
        cluster_arrive_(); cluster_wait_();

        // -------- output: out[b,t] = h2_t . W_out + b_out --------
        float4 hh = *reinterpret_cast<const float4*>(
            h2d + (wp * BPC + wb) * HPITCH + lane * 4);
        float p = hh.x * wo4.x + hh.y * wo4.y + hh.z * wo4.z + hh.w * wo4.w;
        p += __shfl_xor_sync(0xffffffffu, p, 16);
        p += __shfl_xor_sync(0xffffffffu, p, 8);
        p += __shfl_xor_sync(0xffffffffu, p, 4);
        p += __shfl_xor_sync(0xffffffffu, p, 2);
        p += __shfl_xor_sync(0xffffffffu, p, 1);
        if (rank == 0 && lane == 0) out_b[t] = p + boutv;
    }
}

extern "C" void kernel_launch(void* const* d_in, const int* in_sizes, int n_in,
                              void* d_out, int out_size) {
    const float* x    = (const float*)d_in[0];
    const float* wih1 = (const float*)d_in[1];
    const float* whh1 = (const float*)d_in[2];
    const float* bih1 = (const float*)d_in[3];
    const float* bhh1 = (const float*)d_in[4];
    const float* wih2 = (const float*)d_in[5];
    const float* whh2 = (const float*)d_in[6];
    const float* bih2 = (const float*)d_in[7];
    const float* bhh2 = (const float*)d_in[8];
    const float* wout = (const float*)d_in[9];
    const float* bout = (const float*)d_in[10];

    cudaFuncSetAttribute(lstm_persistent_kernel,
                         cudaFuncAttributeMaxDynamicSharedMemorySize, SMEM_BYTES);
    lstm_persistent_kernel<<<(B_TOT / BPC) * CL, NTHREADS, SMEM_BYTES>>>(
        x, wih1, whh1, bih1, bhh1, wih2, whh2, bih2, bhh2, wout, bout, (float*)d_out);
}

// round 17
// speedup vs baseline: 1.5644x; 1.5644x over previous
#include <cuda_runtime.h>
#include <cstdint>

#define T_LEN   1024
#define B_TOT   512
#define CL      4          // cluster size (gate-row split)
#define BPC     16         // batch per cluster
#define MSL     32         // m-slice per CTA (128 / CL)
#define HPITCH  132        // h row pitch (floats): batch stride = 4 banks
#define WPITCH  516        // weight row pitch: [m][4 gates x 128 k] + 4 pad (4 banks)
#define NTHREADS 256       // tid = m_l*8 + ks*4 + bb : 32 m x 2 k-halves x 4 bb
                           // each thread: 4 batches {bb, bb+4, bb+8, bb+12}, half of k

#define W_FLOATS   (32 * WPITCH)
#define H_FLOATS   (2 * BPC * HPITCH)
#define SMEM_FLOATS (3 * W_FLOATS + 2 * H_FLOATS + 2 * BPC)
#define SMEM_BYTES (SMEM_FLOATS * 4)   // 232,064 B <= 232,448 cap

// ---------- f32x2 packed FMA (FFMA2) ----------
__device__ __forceinline__ unsigned long long ffma2(unsigned long long a,
                                                    unsigned long long b,
                                                    unsigned long long c) {
    unsigned long long d;
    asm("fma.rn.f32x2 %0, %1, %2, %3;" : "=l"(d) : "l"(a), "l"(b), "l"(c));
    return d;
}
__device__ __forceinline__ float2 unpk(unsigned long long v) {
    float2 r;
    asm("mov.b64 {%0, %1}, %2;" : "=f"(r.x), "=f"(r.y) : "l"(v));
    return r;
}

// ---------- activations: ex2.approx + Newton-refined reciprocal ----------
__device__ __forceinline__ float rcp_nr(float x) {
    float r; asm("rcp.approx.f32 %0, %1;" : "=f"(r) : "f"(x));
    r = r * fmaf(-x, r, 2.0f);
    return r;
}
__device__ __forceinline__ float ex2f(float x) {
    float r; asm("ex2.approx.f32 %0, %1;" : "=f"(r) : "f"(x)); return r;
}
__device__ __forceinline__ float sigf(float x) {
    return rcp_nr(1.0f + ex2f(-1.4426950408889634f * x));
}
__device__ __forceinline__ float tanh_(float x) {
    return fmaf(-2.0f, rcp_nr(1.0f + ex2f(2.8853900817779268f * x)), 1.0f);
}

// ---------- cluster helpers ----------
__device__ __forceinline__ uint32_t mapa_sh(uint32_t addr, uint32_t rank) {
    uint32_t r;
    asm("mapa.shared::cluster.u32 %0, %1, %2;" : "=r"(r) : "r"(addr), "r"(rank));
    return r;
}
__device__ __forceinline__ void st_cluster_f32(uint32_t addr, float v) {
    asm volatile("st.shared::cluster.f32 [%0], %1;" :: "r"(addr), "f"(v) : "memory");
}
__device__ __forceinline__ void cluster_arrive_() {
    asm volatile("barrier.cluster.arrive.aligned;" ::: "memory");
}
__device__ __forceinline__ void cluster_wait_() {
    asm volatile("barrier.cluster.wait.aligned;" ::: "memory");
}

// 4 gates x 4 batches over this thread's 16 k-chunks (ks folded into hb/wb).
// a[g*4+b] accumulates f32x2 partial sums.
__device__ __forceinline__ void dot4x4(const float* __restrict__ hb,
                                       const float* __restrict__ wb,
                                       unsigned long long* __restrict__ a) {
#pragma unroll
    for (int q = 0; q < 4; ++q) {
#pragma unroll
        for (int j = 0; j < 4; ++j) {
            const int o = q * 32 + j * 4;
            ulonglong2 w0 = *reinterpret_cast<const ulonglong2*>(wb + o);
            ulonglong2 w1 = *reinterpret_cast<const ulonglong2*>(wb + 128 + o);
            ulonglong2 w2 = *reinterpret_cast<const ulonglong2*>(wb + 256 + o);
            ulonglong2 w3 = *reinterpret_cast<const ulonglong2*>(wb + 384 + o);
            ulonglong2 h0 = *reinterpret_cast<const ulonglong2*>(hb + o);
            ulonglong2 h1 = *reinterpret_cast<const ulonglong2*>(hb + 4 * HPITCH + o);
            ulonglong2 h2 = *reinterpret_cast<const ulonglong2*>(hb + 8 * HPITCH + o);
            ulonglong2 h3 = *reinterpret_cast<const ulonglong2*>(hb + 12 * HPITCH + o);
            a[0]  = ffma2(w0.x, h0.x, a[0]);  a[0]  = ffma2(w0.y, h0.y, a[0]);
            a[1]  = ffma2(w0.x, h1.x, a[1]);  a[1]  = ffma2(w0.y, h1.y, a[1]);
            a[2]  = ffma2(w0.x, h2.x, a[2]);  a[2]  = ffma2(w0.y, h2.y, a[2]);
            a[3]  = ffma2(w0.x, h3.x, a[3]);  a[3]  = ffma2(w0.y, h3.y, a[3]);
            a[4]  = ffma2(w1.x, h0.x, a[4]);  a[4]  = ffma2(w1.y, h0.y, a[4]);
            a[5]  = ffma2(w1.x, h1.x, a[5]);  a[5]  = ffma2(w1.y, h1.y, a[5]);
            a[6]  = ffma2(w1.x, h2.x, a[6]);  a[6]  = ffma2(w1.y, h2.y, a[6]);
            a[7]  = ffma2(w1.x, h3.x, a[7]);  a[7]  = ffma2(w1.y, h3.y, a[7]);
            a[8]  = ffma2(w2.x, h0.x, a[8]);  a[8]  = ffma2(w2.y, h0.y, a[8]);
            a[9]  = ffma2(w2.x, h1.x, a[9]);  a[9]  = ffma2(w2.y, h1.y, a[9]);
            a[10] = ffma2(w2.x, h2.x, a[10]); a[10] = ffma2(w2.y, h2.y, a[10]);
            a[11] = ffma2(w2.x, h3.x, a[11]); a[11] = ffma2(w2.y, h3.y, a[11]);
            a[12] = ffma2(w3.x, h0.x, a[12]); a[12] = ffma2(w3.y, h0.y, a[12]);
            a[13] = ffma2(w3.x, h1.x, a[13]); a[13] = ffma2(w3.y, h1.y, a[13]);
            a[14] = ffma2(w3.x, h2.x, a[14]); a[14] = ffma2(w3.y, h2.y, a[14]);
            a[15] = ffma2(w3.x, h3.x, a[15]); a[15] = ffma2(w3.y, h3.y, a[15]);
        }
    }
}

// collapse f32x2 + combine k-halves (partner lane = lane ^ 4); commutative add
__device__ __forceinline__ float ksum(unsigned long long acc) {
    float2 s = unpk(acc);
    float v = s.x + s.y;
    v += __shfl_xor_sync(0xffffffffu, v, 4);
    return v;
}

extern "C" __global__ void __launch_bounds__(NTHREADS, 1) __cluster_dims__(CL, 1, 1)
lstm_persistent_kernel(const float* __restrict__ x,
                       const float* __restrict__ wih1, const float* __restrict__ whh1,
                       const float* __restrict__ bih1, const float* __restrict__ bhh1,
                       const float* __restrict__ wih2, const float* __restrict__ whh2,
                       const float* __restrict__ bih2, const float* __restrict__ bhh2,
                       const float* __restrict__ wout, const float* __restrict__ bout,
                       float* __restrict__ out) {
    extern __shared__ float sm[];
    float* W1  = sm;
    float* W2  = W1 + W_FLOATS;
    float* W3  = W2 + W_FLOATS;
    float* h1d = W3 + W_FLOATS;        // [2][16][HPITCH]
    float* h2d = h1d + H_FLOATS;
    float* xs  = h2d + H_FLOATS;       // [2][16]

    const int tid = threadIdx.x;
    uint32_t rank;
    asm("mov.u32 %0, %%cluster_ctarank;" : "=r"(rank));
    const int cid = blockIdx.x / CL;
    const int m_l = tid >> 3;          // 0..31
    const int ks  = (tid >> 2) & 1;    // k-half (64B-group interleave)
    const int bb  = tid & 3;           // batches bb, bb+4, bb+8, bb+12
    const int m_g = (int)rank * MSL + m_l;

    // ---- load gate-row slices, gate-interleaved: W[m][g*128 + k] ----
    for (int i = tid; i < 4096; i += NTHREADS) {
        int k4 = i & 31, g = (i >> 5) & 3, mi = i >> 7;
        int j = g * 128 + (int)rank * MSL + mi;
        int dst = mi * WPITCH + g * 128;
        reinterpret_cast<float4*>(W1 + dst)[k4] =
            reinterpret_cast<const float4*>(whh1 + (size_t)j * 128)[k4];
        reinterpret_cast<float4*>(W2 + dst)[k4] =
            reinterpret_cast<const float4*>(wih2 + (size_t)j * 128)[k4];
        reinterpret_cast<float4*>(W3 + dst)[k4] =
            reinterpret_cast<const float4*>(whh2 + (size_t)j * 128)[k4];
    }
    for (int i = tid; i < 2 * H_FLOATS; i += NTHREADS) h1d[i] = 0.0f;
    if (tid < BPC) xs[tid] = x[(size_t)(cid * BPC + tid) * T_LEN + 0];
    __syncthreads();
    cluster_arrive_(); cluster_wait_();

    // gate constants (order i, f, g, o), shared by the 4 batches
    const int ji = m_g, jf = 128 + m_g, jg = 256 + m_g, jo = 384 + m_g;
    const float b1c[4] = { bih1[ji] + bhh1[ji], bih1[jf] + bhh1[jf],
                           bih1[jg] + bhh1[jg], bih1[jo] + bhh1[jo] };
    const float wic[4] = { wih1[ji], wih1[jf], wih1[jg], wih1[jo] };
    const float b2c[4] = { bih2[ji] + bhh2[ji], bih2[jf] + bhh2[jf],
                           bih2[jg] + bhh2[jg], bih2[jo] + bhh2[jo] };
    const float boutv = bout[0];

    // per-thread weight bases with ks fold (ks*16 floats = 64B group)
    const float* w1r = W1 + m_l * WPITCH + ks * 16;
    const float* w2r = W2 + m_l * WPITCH + ks * 16;
    const float* w3r = W3 + m_l * WPITCH + ks * 16;

    // store targets: every thread does exactly 2 cluster stores per value.
    // ks=0 -> {self, peer a}; ks=1 -> {peer b, peer c}
    uint32_t h1_sa = (uint32_t)__cvta_generic_to_shared(h1d);
    uint32_t h2_sa = (uint32_t)__cvta_generic_to_shared(h2d);
    uint32_t t1a, t1b, t2a, t2b;
    {
        uint32_t o1 = (rank + 1) & 3, o2 = (rank + 2) & 3, o3 = (rank + 3) & 3;
        if (ks == 0) {
            t1a = mapa_sh(h1_sa, rank); t1b = mapa_sh(h1_sa, o1);
            t2a = mapa_sh(h2_sa, rank); t2b = mapa_sh(h2_sa, o1);
        } else {
            t1a = mapa_sh(h1_sa, o2);   t1b = mapa_sh(h1_sa, o3);
            t2a = mapa_sh(h2_sa, o2);   t2b = mapa_sh(h2_sa, o3);
        }
    }

    // output phase: warp w handles batches w (lanes 0-15) and w+8 (lanes 16-31);
    // each 16-lane half covers 128 dims as 2 float4 per lane.
    const int wb = tid >> 5, lane = tid & 31;
    const int lane16 = lane & 15, half = lane >> 4;
    const int ob = wb + 8 * half;                       // cluster-local batch
    const float4 woa = reinterpret_cast<const float4*>(wout)[lane16 * 2];
    const float4 wob = reinterpret_cast<const float4*>(wout)[lane16 * 2 + 1];
    float* const out_b = out + (size_t)(cid * BPC + ob) * T_LEN;

    float c1[4] = {0, 0, 0, 0}, c2[4] = {0, 0, 0, 0};

    for (int t = 0; t < T_LEN; ++t) {
        const int rp = t & 1, wp = rp ^ 1;
        float xnext = 0.0f;
        if (tid < BPC && t + 1 < T_LEN)
            xnext = x[(size_t)(cid * BPC + tid) * T_LEN + t + 1];
        float xc[4];
#pragma unroll
        for (int jb = 0; jb < 4; ++jb) xc[jb] = xs[rp * BPC + bb + 4 * jb];

        // -------- layer 1: W_hh1 h1[rp] + W_ih1 x + b --------
        unsigned long long a[16];
#pragma unroll
        for (int i = 0; i < 16; ++i) a[i] = 0;
        dot4x4(h1d + (rp * BPC + bb) * HPITCH + ks * 16, w1r, a);

        float h1v[4];
#pragma unroll
        for (int jb = 0; jb < 4; ++jb) {
            float pi = ksum(a[jb])      + fmaf(wic[0], xc[jb], b1c[0]);
            float pf = ksum(a[4 + jb])  + fmaf(wic[1], xc[jb], b1c[1]);
            float pg = ksum(a[8 + jb])  + fmaf(wic[2], xc[jb], b1c[2]);
            float po = ksum(a[12 + jb]) + fmaf(wic[3], xc[jb], b1c[3]);
            c1[jb] = fmaf(sigf(pf), c1[jb], sigf(pi) * tanh_(pg));
            h1v[jb] = sigf(po) * tanh_(c1[jb]);
        }
        {
            const uint32_t off0 = (uint32_t)(((wp * BPC + bb) * HPITCH + m_g) * 4);
#pragma unroll
            for (int jb = 0; jb < 4; ++jb) {
                uint32_t o = off0 + (uint32_t)(jb * 4 * HPITCH * 4);
                st_cluster_f32(t1a + o, h1v[jb]);
                st_cluster_f32(t1b + o, h1v[jb]);
            }
        }
        if (tid < BPC) xs[wp * BPC + tid] = xnext;
        cluster_arrive_();

        // -------- layer 2 part A (legal pre-wait): W_hh2 h2[rp] --------
        // h2[rp] was released by the PREVIOUS step's sync2 -> safe before wait.
#pragma unroll
        for (int i = 0; i < 16; ++i) a[i] = 0;
        dot4x4(h2d + (rp * BPC + bb) * HPITCH + ks * 16, w3r, a);

        cluster_wait_();   // h1[wp] from all CTAs now visible

        // -------- layer 2 part B: += W_ih2 h1[wp] --------
        dot4x4(h1d + (wp * BPC + bb) * HPITCH + ks * 16, w2r, a);

        float h2v[4];
#pragma unroll
        for (int jb = 0; jb < 4; ++jb) {
            float pi = ksum(a[jb])      + b2c[0];
            float pf = ksum(a[4 + jb])  + b2c[1];
            float pg = ksum(a[8 + jb])  + b2c[2];
            float po = ksum(a[12 + jb]) + b2c[3];
            c2[jb] = fmaf(sigf(pf), c2[jb], sigf(pi) * tanh_(pg));
            h2v[jb] = sigf(po) * tanh_(c2[jb]);
        }
        {
            const uint32_t off0 = (uint32_t)(((wp * BPC + bb) * HPITCH + m_g) * 4);
#pragma unroll
            for (int jb = 0; jb < 4; ++jb) {
                uint32_t o = off0 + (uint32_t)(jb * 4 * HPITCH * 4);
                st_cluster_f32(t2a + o, h2v[jb]);
                st_cluster_f32(t2b + o, h2v[jb]);
            }
        }
        cluster_arrive_(); cluster_wait_();

        // -------- output: out[b,t] = h2_t . W_out + b_out --------
        const float* hrow = h2d + (wp * BPC + ob) * HPITCH + lane16 * 8;
        float4 ha = *reinterpret_cast<const float4*>(hrow);
        float4 hb = *reinterpret_cast<const float4*>(hrow + 4);
        float p = ha.x * woa.x + ha.y * woa.y + ha.z * woa.z + ha.w * woa.w
                + hb.x * wob.x + hb.y * wob.y + hb.z * wob.z + hb.w * wob.w;
        p += __shfl_xor_sync(0xffffffffu, p, 8);
        p += __shfl_xor_sync(0xffffffffu, p, 4);
        p += __shfl_xor_sync(0xffffffffu, p, 2);
        p += __shfl_xor_sync(0xffffffffu, p, 1);
        if (rank == 0 && lane16 == 0) out_b[t] = p + boutv;
    }
}

extern "C" void kernel_launch(void* const* d_in, const int* in_sizes, int n_in,
                              void* d_out, int out_size) {
    const float* x    = (const float*)d_in[0];
    const float* wih1 = (const float*)d_in[1];
    const float* whh1 = (const float*)d_in[2];
    const float* bih1 = (const float*)d_in[3];
    const float* bhh1 = (const float*)d_in[4];
    const float* wih2 = (const float*)d_in[5];
    const float* whh2 = (const float*)d_in[6];
    const float* bih2 = (const float*)d_in[7];
    const float* bhh2 = (const float*)d_in[8];
    const float* wout = (const float*)d_in[9];
    const float* bout = (const float*)d_in[10];

    cudaFuncSetAttribute(lstm_persistent_kernel,
                         cudaFuncAttributeMaxDynamicSharedMemorySize, SMEM_BYTES);
    lstm_persistent_kernel<<<(B_TOT / BPC) * CL, NTHREADS, SMEM_BYTES>>>(
        x, wih1, whh1, bih1, bhh1, wih2, whh2, bih2, bhh2, wout, bout, (float*)d_out);
}